// round 6
// baseline (speedup 1.0000x reference)
#include <cuda_runtime.h>
#include <math.h>

// Problem constants (fixed shapes from reference setup_inputs)
#define BATCH 16
#define CIN   128
#define C2    256     // 2*CIN (cos plane + sin plane)
#define COUT  256
#define HW    56
#define PIX   (HW*HW) // 3136
#define TAPS  9

// Scratch (device globals: allocation-free per harness rules)
__device__ __align__(16) float g_inp[BATCH * C2 * PIX];        // [b][c2][y][x], 51.4 MB
__device__ __align__(16) float g_w[C2 * TAPS * 2 * COUT];      // [(c2*9+tap)*2+ri][cout], 4.7 MB

// ---------------------------------------------------------------------------
// Prep 1: input planes  cos(x) -> channels [0,128), sin(x) -> [128,256)
// Pure fp32 (reference is fp32-accurate; TF32 rounding proven wrong in R4).
// ---------------------------------------------------------------------------
__global__ void prep_input(const float* __restrict__ x) {
    int i = blockIdx.x * blockDim.x + threadIdx.x;
    const int total = BATCH * CIN * PIX;
    if (i >= total) return;
    float v = x[i];
    int b   = i / (CIN * PIX);
    int rem = i % (CIN * PIX);
    int c   = rem / PIX;
    int p   = rem % PIX;
    float s, cs;
    sincosf(v, &s, &cs);
    g_inp[(b * C2 + c) * PIX + p]        = cs;
    g_inp[(b * C2 + c + CIN) * PIX + p]  = s;
}

// ---------------------------------------------------------------------------
// Prep 2: trig weight kernels (pure fp32).
// probe/out layout: (1, Cin, Cout, 1, 1, 3, 3) -> flat ((cin*COUT+cout)*9+tap)
// g_w row index for (c2, tap, ri): (c2*9 + tap)*2 + ri, row is COUT wide.
// ---------------------------------------------------------------------------
__global__ void prep_weights(const float* __restrict__ probe,
                             const float* __restrict__ outang) {
    int i = blockIdx.x * blockDim.x + threadIdx.x;
    const int total = CIN * COUT * TAPS;
    if (i >= total) return;
    int cin  = i / (COUT * TAPS);
    int rem  = i % (COUT * TAPS);
    int cout = rem / TAPS;
    int tap  = rem % TAPS;
    float p = probe[i];
    float o = outang[i];
    float sp, cp, so, co;
    sincosf(p, &sp, &cp);
    sincosf(o, &so, &co);
    g_w[(( cin        * TAPS + tap) * 2 + 0) * COUT + cout] = cp * co;
    g_w[(( cin        * TAPS + tap) * 2 + 1) * COUT + cout] = cp * so;
    g_w[(((cin + CIN) * TAPS + tap) * 2 + 0) * COUT + cout] = sp * co;
    g_w[(((cin + CIN) * TAPS + tap) * 2 + 1) * COUT + cout] = sp * so;
}

// ---------------------------------------------------------------------------
// Main conv kernel with chunked + Kahan-compensated accumulation.
// Grid: (4 cout-quarters of 64, 49 spatial tiles of 8x8, 16 batch).
// Block: 256 threads = 16 cout-lanes x 16 pixel-lanes.
// Thread: couts coutBase + ct*4 + 0..3 ; pixels row = pl>>1, cols (pl&1)*4+0..3.
// Accumulation: per 4-channel chunk (36 terms) into plain partial p[],
// then Kahan-merged into (s[], c[]) with __fadd_rn (reassociation-proof).
// This cuts the accumulation-noise amplitude ~4-8x vs flat sequential fp32,
// which quadratically (rel ~ sqrt(a)) cuts atan2 branch-cut flip probability.
// ---------------------------------------------------------------------------
#define CHUNK 4
#define W_FLOATS (CHUNK * TAPS * 2 * 64)    // 4608 floats (64-cout slice)
#define W_VEC4   (W_FLOATS / 4)             // 1152 float4
#define IN_FLOATS (CHUNK * 10 * 10)         // 400 floats

__global__ __launch_bounds__(256)
void ring_conv(float* __restrict__ dout) {
    __shared__ __align__(16) float s_w[W_FLOATS];
    __shared__ float s_in[IN_FLOATS];

    const int tid  = threadIdx.x;
    const int ct   = tid & 15;          // cout lane (4 couts each)
    const int pl   = tid >> 4;          // pixel lane 0..15
    const int row  = pl >> 1;           // 0..7
    const int colb = (pl & 1) * 4;      // 0 or 4

    const int coutBase = blockIdx.x * 64;
    const int t     = blockIdx.y;
    const int tileY = (t / 7) * 8;
    const int tileX = (t % 7) * 8;
    const int b     = blockIdx.z;

    // s = main sum, c = Kahan compensation, p = per-chunk partial
    float sRe[4][4], sIm[4][4];
    float cRe[4][4], cIm[4][4];
#pragma unroll
    for (int j = 0; j < 4; ++j)
#pragma unroll
        for (int k = 0; k < 4; ++k) {
            sRe[j][k] = 0.f; sIm[j][k] = 0.f;
            cRe[j][k] = 0.f; cIm[j][k] = 0.f;
        }

    for (int chunk = 0; chunk < C2 / CHUNK; ++chunk) {
        const int ic0 = chunk * CHUNK;
        __syncthreads();   // protect smem reads of previous chunk

        // ---- load input halo tile: CHUNK x 10 x 10 ----
#pragma unroll
        for (int it = 0; it < 2; ++it) {
            int i = tid + it * 256;
            if (i < IN_FLOATS) {
                int icl = i / 100;
                int p   = i % 100;
                int gy  = tileY + p / 10 - 1;
                int gx  = tileX + p % 10 - 1;
                float v = 0.f;
                if ((unsigned)gy < (unsigned)HW && (unsigned)gx < (unsigned)HW)
                    v = g_inp[((b * C2 + ic0 + icl) * HW + gy) * HW + gx];
                s_in[i] = v;
            }
        }

        // ---- load weights: CHUNK*9*2*64 floats = 1152 float4 ----
#pragma unroll
        for (int it = 0; it < 5; ++it) {
            int i = tid + it * 256;          // float4 index
            if (i < W_VEC4) {
                int f   = i * 4;             // float index (contiguous smem layout)
                int icl = f / (TAPS * 2 * 64);
                int r   = (f % (TAPS * 2 * 64)) / 64;   // tap*2 + ri, 0..17
                int col = f & 63;
                const float4* gp = reinterpret_cast<const float4*>(
                    &g_w[((ic0 + icl) * 18 + r) * COUT + coutBase + col]);
                reinterpret_cast<float4*>(s_w)[i] = *gp;
            }
        }

        __syncthreads();

        // ---- compute chunk partial (36 terms, plain FMA) ----
        float pRe[4][4], pIm[4][4];
#pragma unroll
        for (int j = 0; j < 4; ++j)
#pragma unroll
            for (int k = 0; k < 4; ++k) { pRe[j][k] = 0.f; pIm[j][k] = 0.f; }

#pragma unroll
        for (int icl = 0; icl < CHUNK; ++icl) {
            const float* sin_base = &s_in[icl * 100];
#pragma unroll
            for (int ky = 0; ky < 3; ++ky) {
                float v[6];
                const float* rp = &sin_base[(row + ky) * 10 + colb];
#pragma unroll
                for (int j = 0; j < 6; ++j) v[j] = rp[j];
#pragma unroll
                for (int kx = 0; kx < 3; ++kx) {
                    const int tap = ky * 3 + kx;
                    const float4 wr = reinterpret_cast<const float4*>(
                        &s_w[(icl * 18 + tap * 2 + 0) * 64])[ct];
                    const float4 wi = reinterpret_cast<const float4*>(
                        &s_w[(icl * 18 + tap * 2 + 1) * 64])[ct];
                    float wra[4] = { wr.x, wr.y, wr.z, wr.w };
                    float wia[4] = { wi.x, wi.y, wi.z, wi.w };
#pragma unroll
                    for (int j = 0; j < 4; ++j) {
#pragma unroll
                        for (int k = 0; k < 4; ++k) {
                            float xv = v[k + kx];
                            pRe[j][k] = fmaf(wra[j], xv, pRe[j][k]);
                            pIm[j][k] = fmaf(wia[j], xv, pIm[j][k]);
                        }
                    }
                }
            }
        }

        // ---- Kahan merge of chunk partial into (s, c) ----
        // Implemented with __fadd_rn so the compiler cannot reassociate.
#pragma unroll
        for (int j = 0; j < 4; ++j) {
#pragma unroll
            for (int k = 0; k < 4; ++k) {
                {
                    float y1 = __fadd_rn(pRe[j][k], -cRe[j][k]);
                    float tt = __fadd_rn(sRe[j][k], y1);
                    cRe[j][k] = __fadd_rn(__fadd_rn(tt, -sRe[j][k]), -y1);
                    sRe[j][k] = tt;
                }
                {
                    float y1 = __fadd_rn(pIm[j][k], -cIm[j][k]);
                    float tt = __fadd_rn(sIm[j][k], y1);
                    cIm[j][k] = __fadd_rn(__fadd_rn(tt, -sIm[j][k]), -y1);
                    sIm[j][k] = tt;
                }
            }
        }
    }

    // ---- epilogue: angle = atan2(im, re) ----
    const int y = tileY + row;
#pragma unroll
    for (int j = 0; j < 4; ++j) {
        const int cout = coutBase + ct * 4 + j;
        float* op = &dout[((b * COUT + cout) * HW + y) * HW + tileX + colb];
#pragma unroll
        for (int k = 0; k < 4; ++k)
            op[k] = atan2f(sIm[j][k], sRe[j][k]);
    }
}

// ---------------------------------------------------------------------------
extern "C" void kernel_launch(void* const* d_in, const int* in_sizes, int n_in,
                              void* d_out, int out_size) {
    const float* x      = (const float*)d_in[0];
    const float* probe  = (const float*)d_in[1];
    const float* outang = (const float*)d_in[2];
    float* dout = (float*)d_out;

    (void)in_sizes; (void)n_in; (void)out_size;

    const int n1 = BATCH * CIN * PIX;
    prep_input<<<(n1 + 255) / 256, 256>>>(x);

    const int n2 = CIN * COUT * TAPS;
    prep_weights<<<(n2 + 255) / 256, 256>>>(probe, outang);

    dim3 grid(4, 49, BATCH);
    ring_conv<<<grid, 256>>>(dout);
}

// round 7
// speedup vs baseline: 1.1545x; 1.1545x over previous
#include <cuda_runtime.h>
#include <math.h>

// Problem constants (fixed shapes from reference setup_inputs)
#define BATCH 16
#define CIN   128
#define C2    256     // 2*CIN (cos plane + sin plane)
#define COUT  256
#define HW    56
#define PIX   (HW*HW) // 3136
#define TAPS  9

typedef unsigned long long u64;

// Scratch (device globals: allocation-free per harness rules)
__device__ __align__(16) float g_inp[BATCH * C2 * PIX];        // [b][c2][y][x], 51.4 MB
__device__ __align__(16) float g_w[C2 * TAPS * 2 * COUT];      // [(c2*9+tap)*2+ri][cout], 4.7 MB

// ---- Blackwell packed f32x2 ops (two independent IEEE fp32 lanes) ----
__device__ __forceinline__ u64 fma2(u64 a, u64 b, u64 c) {
    u64 d;
    asm("fma.rn.f32x2 %0, %1, %2, %3;" : "=l"(d) : "l"(a), "l"(b), "l"(c));
    return d;
}
__device__ __forceinline__ u64 add2(u64 a, u64 b) {
    u64 d;
    asm("add.rn.f32x2 %0, %1, %2;" : "=l"(d) : "l"(a), "l"(b));
    return d;
}
// exact IEEE negation of both lanes
#define NEG2(x) ((x) ^ 0x8000000080000000ULL)

__device__ __forceinline__ void unpack2(u64 v, float& lo, float& hi) {
    asm("mov.b64 {%0, %1}, %2;" : "=f"(lo), "=f"(hi) : "l"(v));
}

// ---------------------------------------------------------------------------
// Prep 1: input planes  cos(x) -> channels [0,128), sin(x) -> [128,256)
// Pure fp32 (reference is fp32-accurate; TF32 rounding proven wrong in R4).
// ---------------------------------------------------------------------------
__global__ void prep_input(const float* __restrict__ x) {
    int i = blockIdx.x * blockDim.x + threadIdx.x;
    const int total = BATCH * CIN * PIX;
    if (i >= total) return;
    float v = x[i];
    int b   = i / (CIN * PIX);
    int rem = i % (CIN * PIX);
    int c   = rem / PIX;
    int p   = rem % PIX;
    float s, cs;
    sincosf(v, &s, &cs);
    g_inp[(b * C2 + c) * PIX + p]        = cs;
    g_inp[(b * C2 + c + CIN) * PIX + p]  = s;
}

// ---------------------------------------------------------------------------
// Prep 2: trig weight kernels (pure fp32).
// probe/out layout: (1, Cin, Cout, 1, 1, 3, 3) -> flat ((cin*COUT+cout)*9+tap)
// g_w row index for (c2, tap, ri): (c2*9 + tap)*2 + ri, row is COUT wide.
// ---------------------------------------------------------------------------
__global__ void prep_weights(const float* __restrict__ probe,
                             const float* __restrict__ outang) {
    int i = blockIdx.x * blockDim.x + threadIdx.x;
    const int total = CIN * COUT * TAPS;
    if (i >= total) return;
    int cin  = i / (COUT * TAPS);
    int rem  = i % (COUT * TAPS);
    int cout = rem / TAPS;
    int tap  = rem % TAPS;
    float p = probe[i];
    float o = outang[i];
    float sp, cp, so, co;
    sincosf(p, &sp, &cp);
    sincosf(o, &so, &co);
    g_w[(( cin        * TAPS + tap) * 2 + 0) * COUT + cout] = cp * co;
    g_w[(( cin        * TAPS + tap) * 2 + 1) * COUT + cout] = cp * so;
    g_w[(((cin + CIN) * TAPS + tap) * 2 + 0) * COUT + cout] = sp * co;
    g_w[(((cin + CIN) * TAPS + tap) * 2 + 1) * COUT + cout] = sp * so;
}

// ---------------------------------------------------------------------------
// Main conv kernel: f32x2-packed FMAs over cout-pairs, chunked + Kahan
// (negated-compensation form) accumulation. Bit-identical per-output op
// sequence to the round-6 scalar kernel (each f32x2 lane is one scalar path).
//
// Grid: (4 cout-quarters of 64, 49 spatial tiles of 8x8, 16 batch).
// Block: 256 threads = 16 cout-lanes x 16 pixel-lanes.
// Thread: couts coutBase + ct*4 + {0..3} as two f32x2 pairs;
//         pixels row = pl>>1, cols (pl&1)*4 + 0..3.
// Input halo stored DUPLICATED (v,v) as float2 in smem so the broadcast
// operand of each packed FMA is a single LDS.64 (no pack instructions).
// ---------------------------------------------------------------------------
#define CHUNK 4
#define W_FLOATS (CHUNK * TAPS * 2 * 64)    // 4608 floats (64-cout slice)
#define W_VEC4   (W_FLOATS / 4)             // 1152 float4
#define IN_PTS   (CHUNK * 10 * 10)          // 400 halo points (stored as float2)

__global__ __launch_bounds__(256)
void ring_conv(float* __restrict__ dout) {
    __shared__ __align__(16) float  s_w[W_FLOATS];
    __shared__ __align__(16) float2 s_in[IN_PTS];

    const int tid  = threadIdx.x;
    const int ct   = tid & 15;          // cout lane (4 couts each)
    const int pl   = tid >> 4;          // pixel lane 0..15
    const int row  = pl >> 1;           // 0..7
    const int colb = (pl & 1) * 4;      // 0 or 4

    const int coutBase = blockIdx.x * 64;
    const int t     = blockIdx.y;
    const int tileY = (t / 7) * 8;
    const int tileX = (t % 7) * 8;
    const int b     = blockIdx.z;

    // s = main sum, nc = NEGATED Kahan compensation, p = per-chunk partial.
    // Index [jp][k]: jp = cout pair (couts 2jp, 2jp+1 within this thread's 4),
    // k = pixel column 0..3.
    u64 sRe[2][4], sIm[2][4];
    u64 ncRe[2][4], ncIm[2][4];
#pragma unroll
    for (int jp = 0; jp < 2; ++jp)
#pragma unroll
        for (int k = 0; k < 4; ++k) {
            sRe[jp][k] = 0ull; sIm[jp][k] = 0ull;
            ncRe[jp][k] = 0ull; ncIm[jp][k] = 0ull;   // -0.0 in both lanes
        }

    for (int chunk = 0; chunk < C2 / CHUNK; ++chunk) {
        const int ic0 = chunk * CHUNK;
        __syncthreads();   // protect smem reads of previous chunk

        // ---- load input halo tile: CHUNK x 10 x 10, duplicated (v,v) ----
#pragma unroll
        for (int it = 0; it < 2; ++it) {
            int i = tid + it * 256;
            if (i < IN_PTS) {
                int icl = i / 100;
                int p   = i % 100;
                int gy  = tileY + p / 10 - 1;
                int gx  = tileX + p % 10 - 1;
                float v = 0.f;
                if ((unsigned)gy < (unsigned)HW && (unsigned)gx < (unsigned)HW)
                    v = g_inp[((b * C2 + ic0 + icl) * HW + gy) * HW + gx];
                s_in[i] = make_float2(v, v);
            }
        }

        // ---- load weights: CHUNK*9*2*64 floats = 1152 float4 ----
#pragma unroll
        for (int it = 0; it < 5; ++it) {
            int i = tid + it * 256;          // float4 index
            if (i < W_VEC4) {
                int f   = i * 4;             // float index (contiguous smem layout)
                int icl = f / (TAPS * 2 * 64);
                int r   = (f % (TAPS * 2 * 64)) / 64;   // tap*2 + ri, 0..17
                int col = f & 63;
                const float4* gp = reinterpret_cast<const float4*>(
                    &g_w[((ic0 + icl) * 18 + r) * COUT + coutBase + col]);
                reinterpret_cast<float4*>(s_w)[i] = *gp;
            }
        }

        __syncthreads();

        // ---- compute chunk partial (36 terms per lane, plain packed FMA) ----
        u64 pRe[2][4], pIm[2][4];
#pragma unroll
        for (int jp = 0; jp < 2; ++jp)
#pragma unroll
            for (int k = 0; k < 4; ++k) { pRe[jp][k] = 0ull; pIm[jp][k] = 0ull; }

#pragma unroll
        for (int icl = 0; icl < CHUNK; ++icl) {
            const float2* in_base = &s_in[icl * 100];
#pragma unroll
            for (int ky = 0; ky < 3; ++ky) {
                // 6 duplicated input values as 64-bit (v,v) operands
                u64 vp[6];
                const u64* rp = reinterpret_cast<const u64*>(
                    &in_base[(row + ky) * 10 + colb]);
#pragma unroll
                for (int j = 0; j < 6; ++j) vp[j] = rp[j];
#pragma unroll
                for (int kx = 0; kx < 3; ++kx) {
                    const int tap = ky * 3 + kx;
                    // weight float4 = two f32x2 pairs (couts 0,1 and 2,3)
                    const ulonglong2 wr = reinterpret_cast<const ulonglong2*>(
                        &s_w[(icl * 18 + tap * 2 + 0) * 64])[ct];
                    const ulonglong2 wi = reinterpret_cast<const ulonglong2*>(
                        &s_w[(icl * 18 + tap * 2 + 1) * 64])[ct];
                    u64 wra[2] = { wr.x, wr.y };
                    u64 wia[2] = { wi.x, wi.y };
#pragma unroll
                    for (int jp = 0; jp < 2; ++jp) {
#pragma unroll
                        for (int k = 0; k < 4; ++k) {
                            u64 xv = vp[k + kx];
                            pRe[jp][k] = fma2(wra[jp], xv, pRe[jp][k]);
                            pIm[jp][k] = fma2(wia[jp], xv, pIm[jp][k]);
                        }
                    }
                }
            }
        }

        // ---- Kahan merge (negated-compensation form; exact negation via
        //      sign-bit XOR keeps every step bit-identical to the scalar
        //      __fadd_rn version: y = p - c; t = s + y; c = (t-s)-y ) ----
#pragma unroll
        for (int jp = 0; jp < 2; ++jp) {
#pragma unroll
            for (int k = 0; k < 4; ++k) {
                {
                    u64 y1 = add2(pRe[jp][k], ncRe[jp][k]);
                    u64 tt = add2(sRe[jp][k], y1);
                    ncRe[jp][k] = add2(add2(sRe[jp][k], NEG2(tt)), y1);
                    sRe[jp][k] = tt;
                }
                {
                    u64 y1 = add2(pIm[jp][k], ncIm[jp][k]);
                    u64 tt = add2(sIm[jp][k], y1);
                    ncIm[jp][k] = add2(add2(sIm[jp][k], NEG2(tt)), y1);
                    sIm[jp][k] = tt;
                }
            }
        }
    }

    // ---- epilogue: angle = atan2(im, re) ----
    const int y = tileY + row;
#pragma unroll
    for (int jp = 0; jp < 2; ++jp) {
#pragma unroll
        for (int lane = 0; lane < 2; ++lane) {
            const int cout = coutBase + ct * 4 + jp * 2 + lane;
            float* op = &dout[((b * COUT + cout) * HW + y) * HW + tileX + colb];
#pragma unroll
            for (int k = 0; k < 4; ++k) {
                float reLo, reHi, imLo, imHi;
                unpack2(sRe[jp][k], reLo, reHi);
                unpack2(sIm[jp][k], imLo, imHi);
                float re = lane ? reHi : reLo;
                float im = lane ? imHi : imLo;
                op[k] = atan2f(im, re);
            }
        }
    }
}

// ---------------------------------------------------------------------------
extern "C" void kernel_launch(void* const* d_in, const int* in_sizes, int n_in,
                              void* d_out, int out_size) {
    const float* x      = (const float*)d_in[0];
    const float* probe  = (const float*)d_in[1];
    const float* outang = (const float*)d_in[2];
    float* dout = (float*)d_out;

    (void)in_sizes; (void)n_in; (void)out_size;

    const int n1 = BATCH * CIN * PIX;
    prep_input<<<(n1 + 255) / 256, 256>>>(x);

    const int n2 = CIN * COUT * TAPS;
    prep_weights<<<(n2 + 255) / 256, 256>>>(probe, outang);

    dim3 grid(4, 49, BATCH);
    ring_conv<<<grid, 256>>>(dout);
}